// round 2
// baseline (speedup 1.0000x reference)
#include <cuda_runtime.h>

#define C_GRP 11
#define C_MLP 32
#define NPAIR 66              // upper triangle of 11x11
#define NSTAT 77              // 66 + 11
#define GRID_A 592
#define BLK_A  256
#define PSIZE  0.075f
#define XMIN  -54.0f
#define YMIN  -54.0f
#define CZ    -1.0f           // 0.5*(Z_MIN+Z_MAX)
#define BN_EPS 1e-3f
#define MMAX   131072
#define CAP    64

// static scratch (no dynamic allocation allowed)
__device__ float g_part[GRID_A * 80];      // per-block partial stats
__device__ float g_scale[C_MLP];
__device__ float g_bias[C_MLP];
__device__ int   g_cnt[MMAX];              // points-per-pillar counters
__device__ int   g_slot[MMAX * CAP];       // inverse index: point ids per pillar

// ---------------------------------------------------------------------------
// Stage 0: zero the per-pillar counters (output no longer needs zeroing:
// the pool kernel fully overwrites it)
// ---------------------------------------------------------------------------
__global__ void zero_cnt_kernel(int M) {
    int i = blockIdx.x * blockDim.x + threadIdx.x;
    if (i < M) g_cnt[i] = 0;
}

// ---------------------------------------------------------------------------
// Stage A: accumulate S = sum(g g^T) (66) + s = sum(g) (11), AND scatter each
// point id into its pillar's bucket (counting-sort without a scan).
// ---------------------------------------------------------------------------
__global__ __launch_bounds__(BLK_A)
void stageA_kernel(const float* __restrict__ xyz,
                   const float* __restrict__ ptf,
                   const int*   __restrict__ pil,
                   const int*   __restrict__ psi,
                   int N)
{
    float acc[NPAIR];
    float s[C_GRP];
#pragma unroll
    for (int j = 0; j < NPAIR; j++) acc[j] = 0.f;
#pragma unroll
    for (int j = 0; j < C_GRP; j++) s[j] = 0.f;

    const int stride = GRID_A * BLK_A;
    for (int i = blockIdx.x * BLK_A + threadIdx.x; i < N; i += stride) {
        int p  = psi[i];
        // bucket scatter
        int pos = atomicAdd(&g_cnt[p], 1);
        if (pos < CAP) g_slot[p * CAP + pos] = i;

        int py = pil[3 * p + 1];
        int px = pil[3 * p + 2];
        float cx = ((float)px + 0.5f) * PSIZE + XMIN;
        float cy = ((float)py + 0.5f) * PSIZE + YMIN;
        float x = xyz[3 * i + 0];
        float y = xyz[3 * i + 1];
        float z = xyz[3 * i + 2];
        float g[C_GRP];
        g[0] = x - cx; g[1] = y - cy; g[2] = z - CZ;
        g[3] = x;      g[4] = y;      g[5] = z;
#pragma unroll
        for (int k = 0; k < 5; k++) g[6 + k] = ptf[5 * i + k];

        int j = 0;
#pragma unroll
        for (int a = 0; a < C_GRP; a++) {
            s[a] += g[a];
#pragma unroll
            for (int b = a; b < C_GRP; b++) {
                acc[j] = fmaf(g[a], g[b], acc[j]);
                j++;
            }
        }
    }

    // warp reduction of 77 values
#pragma unroll
    for (int j = 0; j < NPAIR; j++) {
        float v = acc[j];
        v += __shfl_xor_sync(0xffffffffu, v, 16);
        v += __shfl_xor_sync(0xffffffffu, v, 8);
        v += __shfl_xor_sync(0xffffffffu, v, 4);
        v += __shfl_xor_sync(0xffffffffu, v, 2);
        v += __shfl_xor_sync(0xffffffffu, v, 1);
        acc[j] = v;
    }
#pragma unroll
    for (int j = 0; j < C_GRP; j++) {
        float v = s[j];
        v += __shfl_xor_sync(0xffffffffu, v, 16);
        v += __shfl_xor_sync(0xffffffffu, v, 8);
        v += __shfl_xor_sync(0xffffffffu, v, 4);
        v += __shfl_xor_sync(0xffffffffu, v, 2);
        v += __shfl_xor_sync(0xffffffffu, v, 1);
        s[j] = v;
    }

    __shared__ float sm[BLK_A / 32][NSTAT];
    int lane = threadIdx.x & 31;
    int wid  = threadIdx.x >> 5;
    if (lane == 0) {
#pragma unroll
        for (int j = 0; j < NPAIR; j++) sm[wid][j] = acc[j];
#pragma unroll
        for (int j = 0; j < C_GRP; j++) sm[wid][NPAIR + j] = s[j];
    }
    __syncthreads();
    if (threadIdx.x < NSTAT) {
        float t = 0.f;
#pragma unroll
        for (int w = 0; w < BLK_A / 32; w++) t += sm[w][threadIdx.x];
        g_part[blockIdx.x * 80 + threadIdx.x] = t;
    }
}

// ---------------------------------------------------------------------------
// Stage B: reduce partials -> per-channel BN scale/bias
// ---------------------------------------------------------------------------
__global__ void stageB_kernel(const float* __restrict__ W,
                              const float* __restrict__ gamma,
                              const float* __restrict__ beta,
                              int N)
{
    __shared__ float red[NSTAT];
    int t = threadIdx.x;           // 128 threads
    if (t < NSTAT) {
        float a0 = 0.f, a1 = 0.f, a2 = 0.f, a3 = 0.f;
        int b = 0;
        for (; b + 4 <= GRID_A; b += 4) {
            a0 += g_part[(b + 0) * 80 + t];
            a1 += g_part[(b + 1) * 80 + t];
            a2 += g_part[(b + 2) * 80 + t];
            a3 += g_part[(b + 3) * 80 + t];
        }
        for (; b < GRID_A; b++) a0 += g_part[b * 80 + t];
        red[t] = (a0 + a1) + (a2 + a3);
    }
    __syncthreads();
    if (t < C_MLP) {
        float wv[C_GRP];
#pragma unroll
        for (int k = 0; k < C_GRP; k++) wv[k] = W[k * C_MLP + t];
        const float invN = 1.0f / (float)N;

        float mean = 0.f;
#pragma unroll
        for (int k = 0; k < C_GRP; k++) mean = fmaf(wv[k], red[NPAIR + k], mean);
        mean *= invN;

        float ex2 = 0.f;
        int j = 0;
#pragma unroll
        for (int a = 0; a < C_GRP; a++) {
            ex2 = fmaf(wv[a] * wv[a], red[j], ex2);  j++;
#pragma unroll
            for (int b2 = a + 1; b2 < C_GRP; b2++) {
                ex2 = fmaf(2.f * wv[a] * wv[b2], red[j], ex2);  j++;
            }
        }
        ex2 *= invN;

        float var = ex2 - mean * mean;
        float sc  = gamma[t] * rsqrtf(var + BN_EPS);
        g_scale[t] = sc;
        g_bias[t]  = fmaf(-mean, sc, beta[t]);
    }
}

// ---------------------------------------------------------------------------
// Pool: 4 threads per pillar, 8 channels per thread. Walk the pillar's point
// bucket, recompute h = g@W (W in smem as float4), apply BN per point, fmax.
// m init 0 covers both ReLU and empty pillars. No atomics, fully coalesced
// output writes; fully overwrites d_out.
// ---------------------------------------------------------------------------
__global__ __launch_bounds__(256)
void pool_kernel(const float* __restrict__ xyz,
                 const float* __restrict__ ptf,
                 const float* __restrict__ W,
                 const int*   __restrict__ pil,
                 float* __restrict__ out,
                 int M)
{
    __shared__ float4 Ws4[C_GRP * 8];   // 11 rows x 32 cols as float4
    __shared__ float  scs[C_MLP];
    __shared__ float  bss[C_MLP];
    if (threadIdx.x < C_GRP * 8) Ws4[threadIdx.x] = ((const float4*)W)[threadIdx.x];
    if (threadIdx.x >= 128 && threadIdx.x < 160) scs[threadIdx.x - 128] = g_scale[threadIdx.x - 128];
    if (threadIdx.x >= 160 && threadIdx.x < 192) bss[threadIdx.x - 160] = g_bias[threadIdx.x - 160];
    __syncthreads();

    int gt = blockIdx.x * blockDim.x + threadIdx.x;
    int p  = gt >> 2;          // pillar
    int q  = gt & 3;           // channel quad: channels q*8 .. q*8+7
    if (p >= M) return;

    int cnt = g_cnt[p];
    if (cnt > CAP) cnt = CAP;

    float cx = ((float)pil[3 * p + 2] + 0.5f) * PSIZE + XMIN;
    float cy = ((float)pil[3 * p + 1] + 0.5f) * PSIZE + YMIN;

    // hoist this thread's 8 BN params
    float scq[8], bsq[8];
#pragma unroll
    for (int u = 0; u < 8; u++) { scq[u] = scs[q * 8 + u]; bsq[u] = bss[q * 8 + u]; }

    float m[8];
#pragma unroll
    for (int u = 0; u < 8; u++) m[u] = 0.f;

    const int* sl = g_slot + (size_t)p * CAP;
    for (int j = 0; j < cnt; j++) {
        int i = sl[j];
        float x = __ldg(&xyz[3 * i + 0]);
        float y = __ldg(&xyz[3 * i + 1]);
        float z = __ldg(&xyz[3 * i + 2]);
        float g[C_GRP];
        g[0] = x - cx; g[1] = y - cy; g[2] = z - CZ;
        g[3] = x;      g[4] = y;      g[5] = z;
#pragma unroll
        for (int k = 0; k < 5; k++) g[6 + k] = __ldg(&ptf[5 * i + k]);

        float hv[8];
#pragma unroll
        for (int u = 0; u < 8; u++) hv[u] = 0.f;
#pragma unroll
        for (int k = 0; k < C_GRP; k++) {
            float gk = g[k];
            float4 wA = Ws4[k * 8 + q * 2];
            float4 wB = Ws4[k * 8 + q * 2 + 1];
            hv[0] = fmaf(gk, wA.x, hv[0]);
            hv[1] = fmaf(gk, wA.y, hv[1]);
            hv[2] = fmaf(gk, wA.z, hv[2]);
            hv[3] = fmaf(gk, wA.w, hv[3]);
            hv[4] = fmaf(gk, wB.x, hv[4]);
            hv[5] = fmaf(gk, wB.y, hv[5]);
            hv[6] = fmaf(gk, wB.z, hv[6]);
            hv[7] = fmaf(gk, wB.w, hv[7]);
        }
#pragma unroll
        for (int u = 0; u < 8; u++) {
            float yv = fmaf(scq[u], hv[u], bsq[u]);
            m[u] = fmaxf(m[u], yv);
        }
    }

    float4* o = (float4*)(out + (size_t)p * C_MLP + q * 8);
    o[0] = make_float4(m[0], m[1], m[2], m[3]);
    o[1] = make_float4(m[4], m[5], m[6], m[7]);
}

// ---------------------------------------------------------------------------
extern "C" void kernel_launch(void* const* d_in, const int* in_sizes, int n_in,
                              void* d_out, int out_size)
{
    const float* xyz   = (const float*)d_in[0];   // (N,3)
    const float* ptf   = (const float*)d_in[1];   // (N,5)
    const float* W1    = (const float*)d_in[2];   // (11,32)
    const float* gamma = (const float*)d_in[3];   // (32)
    const float* beta  = (const float*)d_in[4];   // (32)
    const int*   pil   = (const int*)d_in[5];     // (M,3)
    const int*   psi   = (const int*)d_in[6];     // (N)
    int N = in_sizes[6];
    int M = in_sizes[5] / 3;
    float* out = (float*)d_out;                   // (M,32)

    zero_cnt_kernel<<<(M + 255) / 256, 256>>>(M);
    stageA_kernel<<<GRID_A, BLK_A>>>(xyz, ptf, pil, psi, N);
    stageB_kernel<<<1, 128>>>(W1, gamma, beta, N);
    pool_kernel<<<(4 * M + 255) / 256, 256>>>(xyz, ptf, W1, pil, out, M);
}